// round 2
// baseline (speedup 1.0000x reference)
#include <cuda_runtime.h>
#include <math.h>

// Problem dims (fixed)
#define Bv 4
#define Sv 1024
#define Dv 1024
#define Hv 16
#define DHv 64
#define Fv 4096
#define Mv (Bv*Sv)   // 4096 tokens

// ---------------- scratch (static device globals; no runtime allocs) --------
__device__ float g_q  [(size_t)Mv*Dv];
__device__ float g_k  [(size_t)Mv*Dv];
__device__ float g_v  [(size_t)Mv*Dv];
__device__ float g_at [(size_t)Mv*Dv];
__device__ float g_h  [(size_t)Mv*Dv];
__device__ float g_tp [(size_t)Mv*Dv];
__device__ float g_ff [(size_t)Mv*Fv];
__device__ float g_sp [(size_t)Mv*Fv];

// ---------------- fp32 SGEMM: C = A[MxK] @ B[KxN] + bias (+ R) --------------
// 128x128 tile, BK=16, 256 threads, 8x8 per-thread micro-tile, smem
// double-buffered with register-staged global prefetch.
__global__ __launch_bounds__(256)
void sgemm_kernel(const float* __restrict__ A, const float* __restrict__ B,
                  const float* __restrict__ bias, const float* __restrict__ R,
                  float* __restrict__ C, int M, int N, int K)
{
    __shared__ float As[2][16][128];   // [k][m] transposed
    __shared__ float Bs[2][16][128];   // [k][n]
    const int tid = threadIdx.x;
    const int tx  = tid & 15;
    const int ty  = tid >> 4;
    const int bm  = blockIdx.y * 128;
    const int bn  = blockIdx.x * 128;

    float acc[8][8];
#pragma unroll
    for (int i = 0; i < 8; i++)
#pragma unroll
        for (int j = 0; j < 8; j++) acc[i][j] = 0.f;

    const int r0  = tid >> 2;          // 0..63  (A rows; second load is +64)
    const int kq0 = (tid & 3) << 2;    // 0,4,8,12
    const int kr0 = tid >> 5;          // 0..7   (B k rows; second is +8)
    const int nq0 = (tid & 31) << 2;   // 0..124

    // prologue: tile 0
    {
        const float* Ag = A + (size_t)bm * K;
        float4 a0 = *(const float4*)(Ag + (size_t)r0 * K + kq0);
        float4 a1 = *(const float4*)(Ag + (size_t)(r0 + 64) * K + kq0);
        As[0][kq0+0][r0] = a0.x; As[0][kq0+1][r0] = a0.y;
        As[0][kq0+2][r0] = a0.z; As[0][kq0+3][r0] = a0.w;
        As[0][kq0+0][r0+64] = a1.x; As[0][kq0+1][r0+64] = a1.y;
        As[0][kq0+2][r0+64] = a1.z; As[0][kq0+3][r0+64] = a1.w;
        const float* Bg = B + bn;
        *(float4*)&Bs[0][kr0  ][nq0] = *(const float4*)(Bg + (size_t)kr0 * N + nq0);
        *(float4*)&Bs[0][kr0+8][nq0] = *(const float4*)(Bg + (size_t)(kr0 + 8) * N + nq0);
    }
    __syncthreads();

    const int nT = K >> 4;
    int buf = 0;
    for (int t = 0; t < nT; t++) {
        float4 pa0, pa1, pb0, pb1;
        if (t + 1 < nT) {
            const float* Ag = A + (size_t)bm * K + (t + 1) * 16;
            const float* Bg = B + (size_t)(t + 1) * 16 * N + bn;
            pa0 = *(const float4*)(Ag + (size_t)r0 * K + kq0);
            pa1 = *(const float4*)(Ag + (size_t)(r0 + 64) * K + kq0);
            pb0 = *(const float4*)(Bg + (size_t)kr0 * N + nq0);
            pb1 = *(const float4*)(Bg + (size_t)(kr0 + 8) * N + nq0);
        }
#pragma unroll
        for (int kk = 0; kk < 16; kk++) {
            float a[8], b[8];
            *(float4*)&a[0] = *(const float4*)&As[buf][kk][ty * 4];
            *(float4*)&a[4] = *(const float4*)&As[buf][kk][64 + ty * 4];
            *(float4*)&b[0] = *(const float4*)&Bs[buf][kk][tx * 4];
            *(float4*)&b[4] = *(const float4*)&Bs[buf][kk][64 + tx * 4];
#pragma unroll
            for (int i = 0; i < 8; i++)
#pragma unroll
                for (int j = 0; j < 8; j++)
                    acc[i][j] = fmaf(a[i], b[j], acc[i][j]);
        }
        if (t + 1 < nT) {
            const int nb = buf ^ 1;
            As[nb][kq0+0][r0] = pa0.x; As[nb][kq0+1][r0] = pa0.y;
            As[nb][kq0+2][r0] = pa0.z; As[nb][kq0+3][r0] = pa0.w;
            As[nb][kq0+0][r0+64] = pa1.x; As[nb][kq0+1][r0+64] = pa1.y;
            As[nb][kq0+2][r0+64] = pa1.z; As[nb][kq0+3][r0+64] = pa1.w;
            *(float4*)&Bs[nb][kr0  ][nq0] = pb0;
            *(float4*)&Bs[nb][kr0+8][nq0] = pb1;
            __syncthreads();
            buf = nb;
        }
    }

    // epilogue: +bias (+residual), float4 stores
    float4 bv0 = *(const float4*)&bias[bn + tx * 4];
    float4 bv1 = *(const float4*)&bias[bn + 64 + tx * 4];
#pragma unroll
    for (int i = 0; i < 8; i++) {
        const int r = (i < 4) ? (ty * 4 + i) : (64 + ty * 4 + (i - 4));
        const size_t off = (size_t)(bm + r) * N + bn;
        float4 o0, o1;
        o0.x = acc[i][0] + bv0.x; o0.y = acc[i][1] + bv0.y;
        o0.z = acc[i][2] + bv0.z; o0.w = acc[i][3] + bv0.w;
        o1.x = acc[i][4] + bv1.x; o1.y = acc[i][5] + bv1.y;
        o1.z = acc[i][6] + bv1.z; o1.w = acc[i][7] + bv1.w;
        if (R) {
            float4 q0 = *(const float4*)(R + off + tx * 4);
            float4 q1 = *(const float4*)(R + off + 64 + tx * 4);
            o0.x += q0.x; o0.y += q0.y; o0.z += q0.z; o0.w += q0.w;
            o1.x += q1.x; o1.y += q1.y; o1.z += q1.z; o1.w += q1.w;
        }
        *(float4*)(C + off + tx * 4)      = o0;
        *(float4*)(C + off + 64 + tx * 4) = o1;
    }
}

// ---------------- causal flash attention, fp32 ------------------------------
// Grid (S/64, H, B), 256 threads. 64x64 Q/K tiles, online softmax.
// Layouts in smem: Qs/Ks d-major [64][68] (padded), Vs [c][64], Ps c-major [64][68].
#define QS(d,r) Qs[(d)*68 + (r)]
#define KS(d,c) Ks[(d)*68 + (c)]
#define VS(c,d) Vs[(c)*64 + (d)]
#define PS(c,r) Ps[(c)*68 + (r)]
#define ATTN_SMEM ((2*64*68 + 64*64 + 64*68) * 4)

__global__ __launch_bounds__(256)
void attn_kernel(const float* __restrict__ Q, const float* __restrict__ Kg,
                 const float* __restrict__ Vg, float* __restrict__ O)
{
    extern __shared__ float sm[];
    float* Qs = sm;
    float* Ks = sm + 64 * 68;
    float* Vs = sm + 2 * 64 * 68;
    float* Ps = sm + 2 * 64 * 68 + 64 * 64;

    const int tid = threadIdx.x;
    const int tx  = tid & 15;
    const int ty  = tid >> 4;
    const int qt  = blockIdx.x;
    const int h   = blockIdx.y;
    const int b   = blockIdx.z;
    const size_t baseQ = ((size_t)b * Sv + (size_t)qt * 64) * Dv + h * 64;

    // load Q tile, pre-scaled by 1/sqrt(64)=0.125 (exact power of 2)
#pragma unroll
    for (int i = 0; i < 4; i++) {
        const int idx = tid + i * 256;
        const int r   = idx >> 4;
        const int d4  = (idx & 15) << 2;
        float4 qv = *(const float4*)(Q + baseQ + (size_t)r * Dv + d4);
        QS(d4+0, r) = qv.x * 0.125f; QS(d4+1, r) = qv.y * 0.125f;
        QS(d4+2, r) = qv.z * 0.125f; QS(d4+3, r) = qv.w * 0.125f;
    }

    float m[4], l[4], acc[4][4];
#pragma unroll
    for (int i = 0; i < 4; i++) {
        m[i] = -1e30f; l[i] = 0.f;
#pragma unroll
        for (int j = 0; j < 4; j++) acc[i][j] = 0.f;
    }

    for (int kt = 0; kt <= qt; kt++) {
        __syncthreads();   // previous iteration's readers of Ks/Vs/Ps done
        const size_t baseK = ((size_t)b * Sv + (size_t)kt * 64) * Dv + h * 64;
#pragma unroll
        for (int i = 0; i < 4; i++) {
            const int idx = tid + i * 256;
            const int c   = idx >> 4;
            const int d4  = (idx & 15) << 2;
            float4 kv = *(const float4*)(Kg + baseK + (size_t)c * Dv + d4);
            KS(d4+0, c) = kv.x; KS(d4+1, c) = kv.y;
            KS(d4+2, c) = kv.z; KS(d4+3, c) = kv.w;
            float4 vv = *(const float4*)(Vg + baseK + (size_t)c * Dv + d4);
            *(float4*)&VS(c, d4) = vv;
        }
        __syncthreads();

        // S = (Q*scale) K^T  (4x4 per thread: rows ty*4+i, cols tx*4+j)
        float s[4][4];
#pragma unroll
        for (int i = 0; i < 4; i++)
#pragma unroll
            for (int j = 0; j < 4; j++) s[i][j] = 0.f;
#pragma unroll 16
        for (int d = 0; d < 64; d++) {
            float4 qv = *(const float4*)&QS(d, ty * 4);
            float4 kv = *(const float4*)&KS(d, tx * 4);
            float qa[4] = {qv.x, qv.y, qv.z, qv.w};
            float ka[4] = {kv.x, kv.y, kv.z, kv.w};
#pragma unroll
            for (int i = 0; i < 4; i++)
#pragma unroll
                for (int j = 0; j < 4; j++)
                    s[i][j] = fmaf(qa[i], ka[j], s[i][j]);
        }

        if (kt == qt) {   // causal mask on the diagonal tile
#pragma unroll
            for (int i = 0; i < 4; i++)
#pragma unroll
                for (int j = 0; j < 4; j++)
                    if (tx * 4 + j > ty * 4 + i) s[i][j] = -1e30f;
        }

        // online softmax update per row (16-lane row group reduction)
#pragma unroll
        for (int i = 0; i < 4; i++) {
            float tm = fmaxf(fmaxf(s[i][0], s[i][1]), fmaxf(s[i][2], s[i][3]));
#pragma unroll
            for (int o = 8; o > 0; o >>= 1)
                tm = fmaxf(tm, __shfl_xor_sync(0xffffffffu, tm, o));
            const float mn = fmaxf(m[i], tm);
            const float sc = expf(m[i] - mn);
            const float p0 = expf(s[i][0] - mn), p1 = expf(s[i][1] - mn);
            const float p2 = expf(s[i][2] - mn), p3 = expf(s[i][3] - mn);
            float rs = (p0 + p1) + (p2 + p3);
#pragma unroll
            for (int o = 8; o > 0; o >>= 1)
                rs += __shfl_xor_sync(0xffffffffu, rs, o);
            l[i] = l[i] * sc + rs;
            m[i] = mn;
#pragma unroll
            for (int j = 0; j < 4; j++) acc[i][j] *= sc;
            PS(tx*4+0, ty*4+i) = p0; PS(tx*4+1, ty*4+i) = p1;
            PS(tx*4+2, ty*4+i) = p2; PS(tx*4+3, ty*4+i) = p3;
        }
        __syncthreads();

        // acc += P @ V  (rows ty*4+i, head-dims tx*4+j)
#pragma unroll 16
        for (int c = 0; c < 64; c++) {
            float4 pv = *(const float4*)&PS(c, ty * 4);
            float4 vv = *(const float4*)&VS(c, tx * 4);
            float pa[4] = {pv.x, pv.y, pv.z, pv.w};
            float va[4] = {vv.x, vv.y, vv.z, vv.w};
#pragma unroll
            for (int i = 0; i < 4; i++)
#pragma unroll
                for (int j = 0; j < 4; j++)
                    acc[i][j] = fmaf(pa[i], va[j], acc[i][j]);
        }
    }

    // write O = acc / l
#pragma unroll
    for (int i = 0; i < 4; i++) {
        const float inv = 1.0f / l[i];
        float4 o;
        o.x = acc[i][0] * inv; o.y = acc[i][1] * inv;
        o.z = acc[i][2] * inv; o.w = acc[i][3] * inv;
        *(float4*)(O + baseQ + (size_t)(ty * 4 + i) * Dv + tx * 4) = o;
    }
}

// ---------------- LayerNorm over D=1024, one CTA per row --------------------
__global__ __launch_bounds__(256)
void ln_kernel(const float* __restrict__ X, const float* __restrict__ gg,
               const float* __restrict__ bb, float* __restrict__ Y)
{
    __shared__ float red[8];
    const int row = blockIdx.x;
    const int tid = threadIdx.x;
    const float* x = X + (size_t)row * Dv;
    float4 v = *(const float4*)(x + tid * 4);

    float s = (v.x + v.y) + (v.z + v.w);
#pragma unroll
    for (int o = 16; o > 0; o >>= 1) s += __shfl_xor_sync(0xffffffffu, s, o);
    if ((tid & 31) == 0) red[tid >> 5] = s;
    __syncthreads();
    float tot = 0.f;
#pragma unroll
    for (int w = 0; w < 8; w++) tot += red[w];
    const float mu = tot * (1.0f / Dv);

    const float d0 = v.x - mu, d1 = v.y - mu, d2 = v.z - mu, d3 = v.w - mu;
    float sq = (d0 * d0 + d1 * d1) + (d2 * d2 + d3 * d3);
    __syncthreads();   // everyone done reading red[] before rewrite
#pragma unroll
    for (int o = 16; o > 0; o >>= 1) sq += __shfl_xor_sync(0xffffffffu, sq, o);
    if ((tid & 31) == 0) red[tid >> 5] = sq;
    __syncthreads();
    float tot2 = 0.f;
#pragma unroll
    for (int w = 0; w < 8; w++) tot2 += red[w];
    const float var = tot2 * (1.0f / Dv);
    const float inv = (float)(1.0 / sqrt((double)(var + 1e-5f)));

    float4 gv = *(const float4*)(gg + tid * 4);
    float4 bvv = *(const float4*)(bb + tid * 4);
    float4 o;
    o.x = d0 * inv * gv.x + bvv.x;
    o.y = d1 * inv * gv.y + bvv.y;
    o.z = d2 * inv * gv.z + bvv.z;
    o.w = d3 * inv * gv.w + bvv.w;
    *(float4*)(Y + (size_t)row * Dv + tid * 4) = o;
}

// ---------------- adaptive LIF scan: sequential over t, 16384 lanes ---------
__global__ __launch_bounds__(256)
void lif_kernel(const float* __restrict__ ff, const float* __restrict__ decay,
                const float* __restrict__ beta, float* __restrict__ spk)
{
    const int idx = blockIdx.x * 256 + threadIdx.x;  // 0..16383
    const int b = idx >> 12;
    const int f = idx & (Fv - 1);
    const float dec = decay[f];
    const float bet = beta[f];
    const float* src = ff + (size_t)b * Sv * Fv + f;
    float* dst = spk + (size_t)b * Sv * Fv + f;

    float vm = 0.f, a = 0.f;
    float xt = src[0];
    for (int t = 0; t < Sv; t++) {
        float xn = (t + 1 < Sv) ? src[(size_t)(t + 1) * Fv] : 0.f;  // prefetch
        vm = fmaf(dec, vm, xt);
        const float u = vm - (1.0f + a);
        const float sp = (u > 0.f) ? 1.0f : 0.f;
        vm = vm * (1.0f - sp);                 // hard reset
        a = fmaf(0.9f, a, bet * sp);           // rho*a + beta*s
        dst[(size_t)t * Fv] = sp;
        xt = xn;
    }
}

// ---------------- launch ----------------------------------------------------
extern "C" void kernel_launch(void* const* d_in, const int* in_sizes, int n_in,
                              void* d_out, int out_size)
{
    const float* x   = (const float*)d_in[0];
    const float* Wq  = (const float*)d_in[1];
    const float* bq  = (const float*)d_in[2];
    const float* Wk  = (const float*)d_in[3];
    const float* bk  = (const float*)d_in[4];
    const float* Wv  = (const float*)d_in[5];
    const float* bv  = (const float*)d_in[6];
    const float* Wo  = (const float*)d_in[7];
    const float* bo  = (const float*)d_in[8];
    const float* g1  = (const float*)d_in[9];
    const float* b1  = (const float*)d_in[10];
    const float* W1  = (const float*)d_in[11];
    const float* bf1 = (const float*)d_in[12];
    const float* W2  = (const float*)d_in[13];
    const float* bf2 = (const float*)d_in[14];
    const float* g2  = (const float*)d_in[15];
    const float* b2  = (const float*)d_in[16];
    const float* dec = (const float*)d_in[17];
    const float* bet = (const float*)d_in[18];
    float* out = (float*)d_out;

    float *pq, *pk, *pv, *pat, *ph, *pt, *pff, *psp;
    cudaGetSymbolAddress((void**)&pq,  g_q);
    cudaGetSymbolAddress((void**)&pk,  g_k);
    cudaGetSymbolAddress((void**)&pv,  g_v);
    cudaGetSymbolAddress((void**)&pat, g_at);
    cudaGetSymbolAddress((void**)&ph,  g_h);
    cudaGetSymbolAddress((void**)&pt,  g_tp);
    cudaGetSymbolAddress((void**)&pff, g_ff);
    cudaGetSymbolAddress((void**)&psp, g_sp);

    cudaFuncSetAttribute(attn_kernel,
                         cudaFuncAttributeMaxDynamicSharedMemorySize, ATTN_SMEM);

    dim3 blk(256);
    // QKV projections
    sgemm_kernel<<<dim3(8, 32), blk>>>(x, Wq, bq, nullptr, pq, Mv, Dv, Dv);
    sgemm_kernel<<<dim3(8, 32), blk>>>(x, Wk, bk, nullptr, pk, Mv, Dv, Dv);
    sgemm_kernel<<<dim3(8, 32), blk>>>(x, Wv, bv, nullptr, pv, Mv, Dv, Dv);
    // causal attention
    attn_kernel<<<dim3(16, 16, 4), blk, ATTN_SMEM>>>(pq, pk, pv, pat);
    // out projection + residual, then LN1
    sgemm_kernel<<<dim3(8, 32), blk>>>(pat, Wo, bo, x, pt, Mv, Dv, Dv);
    ln_kernel<<<Mv, blk>>>(pt, g1, b1, ph);
    // FF1
    sgemm_kernel<<<dim3(32, 32), blk>>>(ph, W1, bf1, nullptr, pff, Mv, Fv, Dv);
    // LIF scan
    lif_kernel<<<64, blk>>>(pff, dec, bet, psp);
    // FF2 + residual h, then LN2 into output
    sgemm_kernel<<<dim3(8, 32), blk>>>(psp, W2, bf2, ph, pt, Mv, Dv, Fv);
    ln_kernel<<<Mv, blk>>>(pt, g2, b2, out);
}

// round 5
// speedup vs baseline: 1.0961x; 1.0961x over previous
#include <cuda_runtime.h>
#include <math.h>

// Problem dims (fixed)
#define Bv 4
#define Sv 1024
#define Dv 1024
#define Hv 16
#define DHv 64
#define Fv 4096
#define Mv (Bv*Sv)   // 4096 tokens

typedef unsigned long long u64t;
union F2 { u64t u; float2 f; };

__device__ __forceinline__ u64t splat2(float x) {
    u64t r; asm("mov.b64 %0, {%1,%1};" : "=l"(r) : "f"(x)); return r;
}
__device__ __forceinline__ void ffma2(u64t& d, u64t a, u64t b) {
    asm("fma.rn.f32x2 %0, %1, %2, %0;" : "+l"(d) : "l"(a), "l"(b));
}

// ---------------- scratch (static device globals; no runtime allocs) --------
__device__ float g_q  [(size_t)Mv*Dv];
__device__ float g_k  [(size_t)Mv*Dv];
__device__ float g_v  [(size_t)Mv*Dv];
__device__ float g_at [(size_t)Mv*Dv];
__device__ float g_h  [(size_t)Mv*Dv];
__device__ float g_tp [(size_t)Mv*Dv];
__device__ float g_ff [(size_t)Mv*Fv];
__device__ float g_sp [(size_t)Mv*Fv];

// ---------------- packed-f32x2 SGEMM: C = A[MxK] @ B[KxN] + bias (+ R) ------
// 128x128 tile, BK=16, 128 threads, 16x8 per-thread micro-tile.
// Accumulators are f32x2 pairs along M: A-pairs come straight out of smem as
// ulonglong2; B values are splat-packed (alu pipe). fma pipe is the limiter.
__global__ __launch_bounds__(128)
void sgemm2_kernel(const float* __restrict__ A, const float* __restrict__ B,
                   const float* __restrict__ bias, const float* __restrict__ R,
                   float* __restrict__ C, int M, int N, int K)
{
    __shared__ __align__(16) float As[2][16][128];   // [k][m]
    __shared__ __align__(16) float Bs[2][16][128];   // [k][n]
    const int tid = threadIdx.x;
    const int tx  = tid & 15;          // col group 0..15
    const int ty  = tid >> 4;          // row group 0..7
    const int r0  = ty * 16;
    const int c0  = tx * 8;
    const int bm  = blockIdx.y * 128;
    const int bn  = blockIdx.x * 128;

    F2 acc[8][8];
#pragma unroll
    for (int p = 0; p < 8; p++)
#pragma unroll
        for (int j = 0; j < 8; j++) acc[p][j].u = 0ull;

    const int arow = tid;              // A staging: one row per thread
    const int bk   = tid >> 3;         // B staging: k row 0..15
    const int bc   = (tid & 7) * 16;   // B staging: col start

    // prologue: tile 0
    {
        const float* Ag = A + (size_t)(bm + arow) * K;
        float4 a0 = ((const float4*)Ag)[0];
        float4 a1 = ((const float4*)Ag)[1];
        float4 a2 = ((const float4*)Ag)[2];
        float4 a3 = ((const float4*)Ag)[3];
        As[0][ 0][arow]=a0.x; As[0][ 1][arow]=a0.y; As[0][ 2][arow]=a0.z; As[0][ 3][arow]=a0.w;
        As[0][ 4][arow]=a1.x; As[0][ 5][arow]=a1.y; As[0][ 6][arow]=a1.z; As[0][ 7][arow]=a1.w;
        As[0][ 8][arow]=a2.x; As[0][ 9][arow]=a2.y; As[0][10][arow]=a2.z; As[0][11][arow]=a2.w;
        As[0][12][arow]=a3.x; As[0][13][arow]=a3.y; As[0][14][arow]=a3.z; As[0][15][arow]=a3.w;
        const float* Bg = B + (size_t)bk * N + bn + bc;
        *(float4*)&Bs[0][bk][bc+ 0] = ((const float4*)Bg)[0];
        *(float4*)&Bs[0][bk][bc+ 4] = ((const float4*)Bg)[1];
        *(float4*)&Bs[0][bk][bc+ 8] = ((const float4*)Bg)[2];
        *(float4*)&Bs[0][bk][bc+12] = ((const float4*)Bg)[3];
    }
    __syncthreads();

    const int nT = K >> 4;
    int buf = 0;
    for (int t = 0; t < nT; t++) {
        float4 pa0, pa1, pa2, pa3, pb0, pb1, pb2, pb3;
        if (t + 1 < nT) {
            const float* Ag = A + (size_t)(bm + arow) * K + (t + 1) * 16;
            pa0 = ((const float4*)Ag)[0];
            pa1 = ((const float4*)Ag)[1];
            pa2 = ((const float4*)Ag)[2];
            pa3 = ((const float4*)Ag)[3];
            const float* Bg = B + (size_t)((t + 1) * 16 + bk) * N + bn + bc;
            pb0 = ((const float4*)Bg)[0];
            pb1 = ((const float4*)Bg)[1];
            pb2 = ((const float4*)Bg)[2];
            pb3 = ((const float4*)Bg)[3];
        }
#pragma unroll
        for (int kk = 0; kk < 16; kk++) {
            const ulonglong2* ap = (const ulonglong2*)&As[buf][kk][r0];
            ulonglong2 a01 = ap[0], a23 = ap[1], a45 = ap[2], a67 = ap[3];
            u64t av[8] = { a01.x, a01.y, a23.x, a23.y, a45.x, a45.y, a67.x, a67.y };
            const float4* bp = (const float4*)&Bs[buf][kk][c0];
            float4 b03 = bp[0], b47 = bp[1];
            u64t bsp[8] = { splat2(b03.x), splat2(b03.y), splat2(b03.z), splat2(b03.w),
                            splat2(b47.x), splat2(b47.y), splat2(b47.z), splat2(b47.w) };
#pragma unroll
            for (int p = 0; p < 8; p++)
#pragma unroll
                for (int j = 0; j < 8; j++)
                    ffma2(acc[p][j].u, av[p], bsp[j]);
        }
        if (t + 1 < nT) {
            const int nb = buf ^ 1;
            As[nb][ 0][arow]=pa0.x; As[nb][ 1][arow]=pa0.y; As[nb][ 2][arow]=pa0.z; As[nb][ 3][arow]=pa0.w;
            As[nb][ 4][arow]=pa1.x; As[nb][ 5][arow]=pa1.y; As[nb][ 6][arow]=pa1.z; As[nb][ 7][arow]=pa1.w;
            As[nb][ 8][arow]=pa2.x; As[nb][ 9][arow]=pa2.y; As[nb][10][arow]=pa2.z; As[nb][11][arow]=pa2.w;
            As[nb][12][arow]=pa3.x; As[nb][13][arow]=pa3.y; As[nb][14][arow]=pa3.z; As[nb][15][arow]=pa3.w;
            *(float4*)&Bs[nb][bk][bc+ 0] = pb0;
            *(float4*)&Bs[nb][bk][bc+ 4] = pb1;
            *(float4*)&Bs[nb][bk][bc+ 8] = pb2;
            *(float4*)&Bs[nb][bk][bc+12] = pb3;
            __syncthreads();
            buf = nb;
        }
    }

    // epilogue: +bias (+residual), float4 stores. acc[p][j]: .x=row r0+2p, .y=row r0+2p+1
    float4 bv0 = *(const float4*)&bias[bn + c0];
    float4 bv1 = *(const float4*)&bias[bn + c0 + 4];
#pragma unroll
    for (int p = 0; p < 8; p++) {
        const size_t off0 = (size_t)(bm + r0 + 2 * p) * N + bn + c0;
        const size_t off1 = off0 + N;
        float4 lo0, lo1, hi0, hi1;
        lo0.x = acc[p][0].f.x + bv0.x; lo0.y = acc[p][1].f.x + bv0.y;
        lo0.z = acc[p][2].f.x + bv0.z; lo0.w = acc[p][3].f.x + bv0.w;
        lo1.x = acc[p][4].f.x + bv1.x; lo1.y = acc[p][5].f.x + bv1.y;
        lo1.z = acc[p][6].f.x + bv1.z; lo1.w = acc[p][7].f.x + bv1.w;
        hi0.x = acc[p][0].f.y + bv0.x; hi0.y = acc[p][1].f.y + bv0.y;
        hi0.z = acc[p][2].f.y + bv0.z; hi0.w = acc[p][3].f.y + bv0.w;
        hi1.x = acc[p][4].f.y + bv1.x; hi1.y = acc[p][5].f.y + bv1.y;
        hi1.z = acc[p][6].f.y + bv1.z; hi1.w = acc[p][7].f.y + bv1.w;
        if (R) {
            float4 r00 = *(const float4*)(R + off0);
            float4 r01 = *(const float4*)(R + off0 + 4);
            float4 r10 = *(const float4*)(R + off1);
            float4 r11 = *(const float4*)(R + off1 + 4);
            lo0.x += r00.x; lo0.y += r00.y; lo0.z += r00.z; lo0.w += r00.w;
            lo1.x += r01.x; lo1.y += r01.y; lo1.z += r01.z; lo1.w += r01.w;
            hi0.x += r10.x; hi0.y += r10.y; hi0.z += r10.z; hi0.w += r10.w;
            hi1.x += r11.x; hi1.y += r11.y; hi1.z += r11.z; hi1.w += r11.w;
        }
        *(float4*)(C + off0)     = lo0;
        *(float4*)(C + off0 + 4) = lo1;
        *(float4*)(C + off1)     = hi0;
        *(float4*)(C + off1 + 4) = hi1;
    }
}

// ---------------- causal flash attention, fp32 (unchanged) ------------------
#define QS(d,r) Qs[(d)*68 + (r)]
#define KS(d,c) Ks[(d)*68 + (c)]
#define VS(c,d) Vs[(c)*64 + (d)]
#define PS(c,r) Ps[(c)*68 + (r)]
#define ATTN_SMEM ((2*64*68 + 64*64 + 64*68) * 4)

__global__ __launch_bounds__(256)
void attn_kernel(const float* __restrict__ Q, const float* __restrict__ Kg,
                 const float* __restrict__ Vg, float* __restrict__ O)
{
    extern __shared__ float sm[];
    float* Qs = sm;
    float* Ks = sm + 64 * 68;
    float* Vs = sm + 2 * 64 * 68;
    float* Ps = sm + 2 * 64 * 68 + 64 * 64;

    const int tid = threadIdx.x;
    const int tx  = tid & 15;
    const int ty  = tid >> 4;
    const int qt  = blockIdx.x;
    const int h   = blockIdx.y;
    const int b   = blockIdx.z;
    const size_t baseQ = ((size_t)b * Sv + (size_t)qt * 64) * Dv + h * 64;

#pragma unroll
    for (int i = 0; i < 4; i++) {
        const int idx = tid + i * 256;
        const int r   = idx >> 4;
        const int d4  = (idx & 15) << 2;
        float4 qv = *(const float4*)(Q + baseQ + (size_t)r * Dv + d4);
        QS(d4+0, r) = qv.x * 0.125f; QS(d4+1, r) = qv.y * 0.125f;
        QS(d4+2, r) = qv.z * 0.125f; QS(d4+3, r) = qv.w * 0.125f;
    }

    float m[4], l[4], acc[4][4];
#pragma unroll
    for (int i = 0; i < 4; i++) {
        m[i] = -1e30f; l[i] = 0.f;
#pragma unroll
        for (int j = 0; j < 4; j++) acc[i][j] = 0.f;
    }

    for (int kt = 0; kt <= qt; kt++) {
        __syncthreads();
        const size_t baseK = ((size_t)b * Sv + (size_t)kt * 64) * Dv + h * 64;
#pragma unroll
        for (int i = 0; i < 4; i++) {
            const int idx = tid + i * 256;
            const int c   = idx >> 4;
            const int d4  = (idx & 15) << 2;
            float4 kv = *(const float4*)(Kg + baseK + (size_t)c * Dv + d4);
            KS(d4+0, c) = kv.x; KS(d4+1, c) = kv.y;
            KS(d4+2, c) = kv.z; KS(d4+3, c) = kv.w;
            float4 vv = *(const float4*)(Vg + baseK + (size_t)c * Dv + d4);
            *(float4*)&VS(c, d4) = vv;
        }
        __syncthreads();

        float s[4][4];
#pragma unroll
        for (int i = 0; i < 4; i++)
#pragma unroll
            for (int j = 0; j < 4; j++) s[i][j] = 0.f;
#pragma unroll 16
        for (int d = 0; d < 64; d++) {
            float4 qv = *(const float4*)&QS(d, ty * 4);
            float4 kv = *(const float4*)&KS(d, tx * 4);
            float qa[4] = {qv.x, qv.y, qv.z, qv.w};
            float ka[4] = {kv.x, kv.y, kv.z, kv.w};
#pragma unroll
            for (int i = 0; i < 4; i++)
#pragma unroll
                for (int j = 0; j < 4; j++)
                    s[i][j] = fmaf(qa[i], ka[j], s[i][j]);
        }

        if (kt == qt) {
#pragma unroll
            for (int i = 0; i < 4; i++)
#pragma unroll
                for (int j = 0; j < 4; j++)
                    if (tx * 4 + j > ty * 4 + i) s[i][j] = -1e30f;
        }

#pragma unroll
        for (int i = 0; i < 4; i++) {
            float tm = fmaxf(fmaxf(s[i][0], s[i][1]), fmaxf(s[i][2], s[i][3]));
#pragma unroll
            for (int o = 8; o > 0; o >>= 1)
                tm = fmaxf(tm, __shfl_xor_sync(0xffffffffu, tm, o));
            const float mn = fmaxf(m[i], tm);
            const float sc = expf(m[i] - mn);
            const float p0 = expf(s[i][0] - mn), p1 = expf(s[i][1] - mn);
            const float p2 = expf(s[i][2] - mn), p3 = expf(s[i][3] - mn);
            float rs = (p0 + p1) + (p2 + p3);
#pragma unroll
            for (int o = 8; o > 0; o >>= 1)
                rs += __shfl_xor_sync(0xffffffffu, rs, o);
            l[i] = l[i] * sc + rs;
            m[i] = mn;
#pragma unroll
            for (int j = 0; j < 4; j++) acc[i][j] *= sc;
            PS(tx*4+0, ty*4+i) = p0; PS(tx*4+1, ty*4+i) = p1;
            PS(tx*4+2, ty*4+i) = p2; PS(tx*4+3, ty*4+i) = p3;
        }
        __syncthreads();

#pragma unroll 16
        for (int c = 0; c < 64; c++) {
            float4 pv = *(const float4*)&PS(c, ty * 4);
            float4 vv = *(const float4*)&VS(c, tx * 4);
            float pa[4] = {pv.x, pv.y, pv.z, pv.w};
            float va[4] = {vv.x, vv.y, vv.z, vv.w};
#pragma unroll
            for (int i = 0; i < 4; i++)
#pragma unroll
                for (int j = 0; j < 4; j++)
                    acc[i][j] = fmaf(pa[i], va[j], acc[i][j]);
        }
    }

#pragma unroll
    for (int i = 0; i < 4; i++) {
        const float inv = 1.0f / l[i];
        float4 o;
        o.x = acc[i][0] * inv; o.y = acc[i][1] * inv;
        o.z = acc[i][2] * inv; o.w = acc[i][3] * inv;
        *(float4*)(O + baseQ + (size_t)(ty * 4 + i) * Dv + tx * 4) = o;
    }
}

// ---------------- LayerNorm over D=1024, one CTA per row --------------------
__global__ __launch_bounds__(256)
void ln_kernel(const float* __restrict__ X, const float* __restrict__ gg,
               const float* __restrict__ bb, float* __restrict__ Y)
{
    __shared__ float red[8];
    const int row = blockIdx.x;
    const int tid = threadIdx.x;
    const float* x = X + (size_t)row * Dv;
    float4 v = *(const float4*)(x + tid * 4);

    float s = (v.x + v.y) + (v.z + v.w);
#pragma unroll
    for (int o = 16; o > 0; o >>= 1) s += __shfl_xor_sync(0xffffffffu, s, o);
    if ((tid & 31) == 0) red[tid >> 5] = s;
    __syncthreads();
    float tot = 0.f;
#pragma unroll
    for (int w = 0; w < 8; w++) tot += red[w];
    const float mu = tot * (1.0f / Dv);

    const float d0 = v.x - mu, d1 = v.y - mu, d2 = v.z - mu, d3 = v.w - mu;
    float sq = (d0 * d0 + d1 * d1) + (d2 * d2 + d3 * d3);
    __syncthreads();
#pragma unroll
    for (int o = 16; o > 0; o >>= 1) sq += __shfl_xor_sync(0xffffffffu, sq, o);
    if ((tid & 31) == 0) red[tid >> 5] = sq;
    __syncthreads();
    float tot2 = 0.f;
#pragma unroll
    for (int w = 0; w < 8; w++) tot2 += red[w];
    const float var = tot2 * (1.0f / Dv);
    const float inv = (float)(1.0 / sqrt((double)(var + 1e-5f)));

    float4 gv = *(const float4*)(gg + tid * 4);
    float4 bvv = *(const float4*)(bb + tid * 4);
    float4 o;
    o.x = d0 * inv * gv.x + bvv.x;
    o.y = d1 * inv * gv.y + bvv.y;
    o.z = d2 * inv * gv.z + bvv.z;
    o.w = d3 * inv * gv.w + bvv.w;
    *(float4*)(Y + (size_t)row * Dv + tid * 4) = o;
}

// ---------------- adaptive LIF scan: depth-8 load pipeline ------------------
__global__ __launch_bounds__(128)
void lif_kernel(const float* __restrict__ ff, const float* __restrict__ decay,
                const float* __restrict__ beta, float* __restrict__ spk)
{
    const int idx = blockIdx.x * 128 + threadIdx.x;  // 0..16383
    const int b = idx >> 12;
    const int f = idx & (Fv - 1);
    const float dec = decay[f];
    const float bet = beta[f];
    const float* src = ff + (size_t)b * Sv * Fv + f;
    float* dst = spk + (size_t)b * Sv * Fv + f;

    float buf[8];
#pragma unroll
    for (int i = 0; i < 8; i++) buf[i] = src[(size_t)i * Fv];

    float vm = 0.f, a = 0.f;
    for (int t = 0; t < Sv; t += 8) {
#pragma unroll
        for (int u = 0; u < 8; u++) {
            const float xt = buf[u];
            const int tn = t + u + 8;
            if (tn < Sv) buf[u] = src[(size_t)tn * Fv];
            vm = fmaf(dec, vm, xt);
            const float uu = vm - (1.0f + a);
            const float sp = (uu > 0.f) ? 1.0f : 0.f;
            vm = vm * (1.0f - sp);
            a = fmaf(0.9f, a, bet * sp);
            dst[(size_t)(t + u) * Fv] = sp;
        }
    }
}

// ---------------- launch ----------------------------------------------------
extern "C" void kernel_launch(void* const* d_in, const int* in_sizes, int n_in,
                              void* d_out, int out_size)
{
    const float* x   = (const float*)d_in[0];
    const float* Wq  = (const float*)d_in[1];
    const float* bq  = (const float*)d_in[2];
    const float* Wk  = (const float*)d_in[3];
    const float* bk  = (const float*)d_in[4];
    const float* Wv  = (const float*)d_in[5];
    const float* bv  = (const float*)d_in[6];
    const float* Wo  = (const float*)d_in[7];
    const float* bo  = (const float*)d_in[8];
    const float* g1  = (const float*)d_in[9];
    const float* b1  = (const float*)d_in[10];
    const float* W1  = (const float*)d_in[11];
    const float* bf1 = (const float*)d_in[12];
    const float* W2  = (const float*)d_in[13];
    const float* bf2 = (const float*)d_in[14];
    const float* g2  = (const float*)d_in[15];
    const float* b2  = (const float*)d_in[16];
    const float* dec = (const float*)d_in[17];
    const float* bet = (const float*)d_in[18];
    float* out = (float*)d_out;

    float *pq, *pk, *pv, *pat, *ph, *pt, *pff, *psp;
    cudaGetSymbolAddress((void**)&pq,  g_q);
    cudaGetSymbolAddress((void**)&pk,  g_k);
    cudaGetSymbolAddress((void**)&pv,  g_v);
    cudaGetSymbolAddress((void**)&pat, g_at);
    cudaGetSymbolAddress((void**)&ph,  g_h);
    cudaGetSymbolAddress((void**)&pt,  g_tp);
    cudaGetSymbolAddress((void**)&pff, g_ff);
    cudaGetSymbolAddress((void**)&psp, g_sp);

    cudaFuncSetAttribute(attn_kernel,
                         cudaFuncAttributeMaxDynamicSharedMemorySize, ATTN_SMEM);

    dim3 blk128(128);
    dim3 blk256(256);
    // QKV projections
    sgemm2_kernel<<<dim3(8, 32), blk128>>>(x, Wq, bq, nullptr, pq, Mv, Dv, Dv);
    sgemm2_kernel<<<dim3(8, 32), blk128>>>(x, Wk, bk, nullptr, pk, Mv, Dv, Dv);
    sgemm2_kernel<<<dim3(8, 32), blk128>>>(x, Wv, bv, nullptr, pv, Mv, Dv, Dv);
    // causal attention
    attn_kernel<<<dim3(16, 16, 4), blk256, ATTN_SMEM>>>(pq, pk, pv, pat);
    // out projection + residual, then LN1
    sgemm2_kernel<<<dim3(8, 32), blk128>>>(pat, Wo, bo, x, pt, Mv, Dv, Dv);
    ln_kernel<<<Mv, blk256>>>(pt, g1, b1, ph);
    // FF1
    sgemm2_kernel<<<dim3(32, 32), blk128>>>(ph, W1, bf1, nullptr, pff, Mv, Fv, Dv);
    // LIF scan
    lif_kernel<<<128, blk128>>>(pff, dec, bet, psp);
    // FF2 + residual h, then LN2 into output
    sgemm2_kernel<<<dim3(8, 32), blk128>>>(psp, W2, bf2, ph, pt, Mv, Dv, Fv);
    ln_kernel<<<Mv, blk256>>>(pt, g2, b2, out);
}